// round 2
// baseline (speedup 1.0000x reference)
#include <cuda_runtime.h>
#include <cuda_bf16.h>
#include <cstdint>

typedef unsigned long long ull;

#define EPSV 1e-5f

// ---------------- device scratch (no allocations allowed) ----------------
__device__ float  g_h[8*64*64*128];        // BN-ReLU output NHWC [b][y][x][c]
__device__ float  g_off[8*64*64*18];       // offsets [b][y][x][18]
__device__ float2 g_woff2[9*64*18];        // w_off repack [tap][c2][oc] float2(c even,odd)
__device__ float4 g_wq[9*128*32];          // w_dconv repack [k][c][o4] float4 over o

// ---------------- f32x2 helpers ----------------
__device__ __forceinline__ ull f32x2_add(ull a, ull b){
    ull r; asm("add.rn.f32x2 %0, %1, %2;" : "=l"(r) : "l"(a), "l"(b)); return r;
}
__device__ __forceinline__ void f32x2_fma(ull &d, ull a, ull b){
    asm("fma.rn.f32x2 %0, %1, %2, %0;" : "+l"(d) : "l"(a), "l"(b));
}
__device__ __forceinline__ ull f32x2_pack(float lo, float hi){
    ull r; asm("mov.b64 %0, {%1, %2};" : "=l"(r) : "f"(lo), "f"(hi)); return r;
}
__device__ __forceinline__ float2 f32x2_unpack(ull v){
    float2 f; asm("mov.b64 {%0, %1}, %2;" : "=f"(f.x), "=f"(f.y) : "l"(v)); return f;
}
__device__ __forceinline__ void lds_2u64(ull &a, ull &b, uint32_t addr){
    asm volatile("ld.shared.v2.b64 {%0, %1}, [%2];" : "=l"(a), "=l"(b) : "r"(addr));
}

// ---------------- kernel 0: weight repack ----------------
__global__ void k_prep(const float* __restrict__ woff, const float* __restrict__ wdc)
{
    int i = blockIdx.x*256 + threadIdx.x;
    if (i < 9*64*18) {
        int tap = i / 1152;
        int r   = i - tap*1152;
        int c2  = r / 18, oc = r - c2*18;
        g_woff2[i] = make_float2(woff[(oc*128 + 2*c2    )*9 + tap],
                                 woff[(oc*128 + 2*c2 + 1)*9 + tap]);
    }
    if (i < 9*128*32) {
        int k  = i / 4096;
        int r  = i - k*4096;
        int c  = r / 32, o4 = r - c*32;
        const float* s = wdc + (size_t)(o4*4)*1152 + c*9 + k;   // wdc[o][c][kk]
        g_wq[i] = make_float4(s[0], s[1152], s[2304], s[3456]);
    }
}

// ---------------- kernel 1: BN + ReLU, NCHW -> NHWC ----------------
__global__ __launch_bounds__(256) void k_bnrelu(const float* __restrict__ x,
    const float* __restrict__ gam, const float* __restrict__ bet,
    const float* __restrict__ mea, const float* __restrict__ var)
{
    __shared__ float s[128*65];
    const int t = threadIdx.x;
    const int b = blockIdx.x, y = blockIdx.y;
    #pragma unroll
    for (int i0 = 0; i0 < 8192; i0 += 256) {
        int i = i0 + t;
        int c = i >> 6, xx = i & 63;
        float val = x[(((size_t)b*128 + c)*64 + y)*64 + xx];
        float inv = __ldg(gam + c) * rsqrtf(__ldg(var + c) + EPSV);
        s[c*65 + xx] = fmaxf((val - __ldg(mea + c)) * inv + __ldg(bet + c), 0.f);
    }
    __syncthreads();
    float* hrow = g_h + ((size_t)b*64 + y)*64*128;
    #pragma unroll
    for (int i0 = 0; i0 < 8192; i0 += 256) {
        int i = i0 + t;
        int xx = i >> 7, c = i & 127;
        hrow[xx*128 + c] = s[c*65 + xx];
    }
}

// ---------------- kernel 2: offset conv (18 out channels) ----------------
// grid (8,64), 256 thr = 64 px * 4 channel-slices. smem: vrow [xx][c] stride 132
// + per-ky weights [kx][c2][18] float2. Lane-interleaved c2 = 4*c2p + sl keeps
// weight LDS conflict-free (sl stride 144B = 16 mod 128).
__global__ __launch_bounds__(256, 2) void k_off(const float* __restrict__ boff)
{
    extern __shared__ float sm2[];
    float* vrow = sm2;            // 64*132 floats
    float* wk   = sm2 + 64*132;   // 3*64*18 float2 = 6912 floats
    const int t = threadIdx.x;
    const int b = blockIdx.x, y = blockIdx.y;
    const int px = t >> 2, sl = t & 3;
    const uint32_t vrb = (uint32_t)__cvta_generic_to_shared(vrow);
    const uint32_t wkb = (uint32_t)__cvta_generic_to_shared(wk);

    ull acc[18];
    #pragma unroll
    for (int o = 0; o < 18; ++o) acc[o] = 0ull;

    for (int ky = 0; ky < 3; ++ky) {
        __syncthreads();
        const int yy = y + ky - 1;
        if ((unsigned)yy < 64u) {
            const float* src = g_h + ((size_t)b*64 + yy)*64*128;
            for (int i = t; i < 8192; i += 256) vrow[(i>>7)*132 + (i&127)] = src[i];
        } else {
            for (int i = t; i < 8192; i += 256) vrow[(i>>7)*132 + (i&127)] = 0.f;
        }
        {
            float4* dst = (float4*)wk;
            const float4* s = (const float4*)(g_woff2 + ky*3*64*18);
            for (int i = t; i < 1728; i += 256) dst[i] = s[i];
        }
        __syncthreads();
        #pragma unroll
        for (int kx = 0; kx < 3; ++kx) {
            const int xx = px + kx - 1;
            const bool valid = (unsigned)xx < 64u;
            const uint32_t vba = vrb + (uint32_t)xx*528u;
            #pragma unroll
            for (int c2p = 0; c2p < 16; ++c2p) {
                const int c2 = c2p*4 + sl;
                ull v = 0ull;
                if (valid)
                    asm volatile("ld.shared.b64 %0, [%1];" : "=l"(v) : "r"(vba + (uint32_t)c2*8u));
                const uint32_t wa = wkb + (uint32_t)((kx*64 + c2)*144);
                #pragma unroll
                for (int oq = 0; oq < 9; ++oq) {
                    ull wA, wB;
                    lds_2u64(wA, wB, wa + (uint32_t)oq*16u);
                    f32x2_fma(acc[2*oq  ], v, wA);
                    f32x2_fma(acc[2*oq+1], v, wB);
                }
            }
        }
    }
    // reduce over 4 slices (lane bits 0,1)
    #pragma unroll
    for (int o = 0; o < 18; ++o) {
        ull v = acc[o];
        v = f32x2_add(v, __shfl_xor_sync(0xFFFFFFFFu, v, 1));
        v = f32x2_add(v, __shfl_xor_sync(0xFFFFFFFFu, v, 2));
        acc[o] = v;
    }
    if (sl == 0) {
        float* orow = g_off + (((size_t)b*64 + y)*64 + px)*18;
        #pragma unroll
        for (int o = 0; o < 18; ++o) {
            float2 f = f32x2_unpack(acc[o]);
            orow[o] = f.x + f.y + __ldg(boff + o);
        }
    }
}

// ---------------- kernel 3: deformable conv ----------------
// grid (8,64), 256 thr, 2 CTAs/SM. Per tap: bilinear-stage v[64px][128c] + W_k,
// then f32x2 GEMM, thread tile 8px x 4oc (acc packed over o-pairs).
__global__ __launch_bounds__(256, 2) void k_deform(const float* __restrict__ bdc,
                                                   float* __restrict__ out)
{
    extern __shared__ float sm3[];
    float* vbuf = sm3;                 // 8192 floats: v [px][c]
    float* wsm  = sm3 + 8192;          // 16384 floats: W_k [c][o4] float4 / epilogue
    float* offs = sm3 + 8192 + 16384;  // 1152 floats: [px][18]
    const int t = threadIdx.x;
    const int b = blockIdx.x, y = blockIdx.y;
    const int lane = t & 31, warp = t >> 5;

    {
        const float* orow = g_off + ((size_t)b*64 + y)*64*18;
        for (int i = t; i < 1152; i += 256) offs[i] = orow[i];
    }

    ull acc[16];
    #pragma unroll
    for (int i = 0; i < 16; ++i) acc[i] = 0ull;

    const float* hbase = g_h + (size_t)b*4096*128 + lane*4;
    const float4* vb4 = (const float4*)vbuf;
    const longlong2* wb2 = (const longlong2*)wsm;

    for (int k = 0; k < 9; ++k) {
        __syncthreads();   // prev GEMM / offs staging complete
        // stage W_k (coalesced 64KB)
        {
            float4* dst = (float4*)wsm;
            const float4* src = g_wq + k*4096;
            for (int i = t; i < 4096; i += 256) dst[i] = src[i];
        }
        // stage bilinear samples: warp owns 8 px, lanes cover 128 c as float4
        const int ky = k/3 - 1, kx = k - (k/3)*3 - 1;
        #pragma unroll
        for (int pp = 0; pp < 8; ++pp) {
            const int px = warp*8 + pp;
            const float dy = offs[px*18 + 2*k];
            const float dx = offs[px*18 + 2*k + 1];
            const float py  = (float)(y + ky) + dy;
            const float pxf = (float)(px + kx) + dx;
            const float fy = floorf(py), fx = floorf(pxf);
            const int y0 = (int)fy, x0 = (int)fx;
            const float wy = py - fy, wx = pxf - fx;
            const float w00 = (1.f-wy)*(1.f-wx), w01 = (1.f-wy)*wx;
            const float w10 = wy*(1.f-wx),       w11 = wy*wx;
            const int y1 = y0 + 1, x1 = x0 + 1;
            float4 r = make_float4(0.f,0.f,0.f,0.f);
            if ((unsigned)y0 < 64u) {
                const float* rp = hbase + (size_t)y0*8192;
                if ((unsigned)x0 < 64u) { float4 c = *(const float4*)(rp + x0*128);
                    r.x += w00*c.x; r.y += w00*c.y; r.z += w00*c.z; r.w += w00*c.w; }
                if ((unsigned)x1 < 64u) { float4 c = *(const float4*)(rp + x1*128);
                    r.x += w01*c.x; r.y += w01*c.y; r.z += w01*c.z; r.w += w01*c.w; }
            }
            if ((unsigned)y1 < 64u) {
                const float* rp = hbase + (size_t)y1*8192;
                if ((unsigned)x0 < 64u) { float4 c = *(const float4*)(rp + x0*128);
                    r.x += w10*c.x; r.y += w10*c.y; r.z += w10*c.z; r.w += w10*c.w; }
                if ((unsigned)x1 < 64u) { float4 c = *(const float4*)(rp + x1*128);
                    r.x += w11*c.x; r.y += w11*c.y; r.z += w11*c.z; r.w += w11*c.w; }
            }
            ((float4*)(vbuf + px*128))[lane] = r;
        }
        __syncthreads();
        // GEMM: out[px][o] += v[px][c] * W[o][c][k]
        #pragma unroll 4
        for (int c4 = 0; c4 < 32; ++c4) {
            longlong2 w0 = wb2[(c4*4 + 0)*32 + lane];
            longlong2 w1 = wb2[(c4*4 + 1)*32 + lane];
            longlong2 w2 = wb2[(c4*4 + 2)*32 + lane];
            longlong2 w3 = wb2[(c4*4 + 3)*32 + lane];
            #pragma unroll
            for (int pp = 0; pp < 8; ++pp) {
                float4 v = vb4[(warp*8 + pp)*32 + c4];
                ull v0 = f32x2_pack(v.x, v.x);
                ull v1 = f32x2_pack(v.y, v.y);
                ull v2 = f32x2_pack(v.z, v.z);
                ull v3 = f32x2_pack(v.w, v.w);
                f32x2_fma(acc[pp*2  ], v0, (ull)w0.x);
                f32x2_fma(acc[pp*2+1], v0, (ull)w0.y);
                f32x2_fma(acc[pp*2  ], v1, (ull)w1.x);
                f32x2_fma(acc[pp*2+1], v1, (ull)w1.y);
                f32x2_fma(acc[pp*2  ], v2, (ull)w2.x);
                f32x2_fma(acc[pp*2+1], v2, (ull)w2.y);
                f32x2_fma(acc[pp*2  ], v3, (ull)w3.x);
                f32x2_fma(acc[pp*2+1], v3, (ull)w3.y);
            }
        }
    }
    __syncthreads();
    // epilogue: transpose through smem (reuse wsm) then coalesced NCHW stores
    float* epi = wsm;  // [o][px] stride 65
    #pragma unroll
    for (int pp = 0; pp < 8; ++pp) {
        const int px = warp*8 + pp;
        float2 a = f32x2_unpack(acc[pp*2    ]);
        float2 c = f32x2_unpack(acc[pp*2 + 1]);
        epi[(lane*4 + 0)*65 + px] = a.x;
        epi[(lane*4 + 1)*65 + px] = a.y;
        epi[(lane*4 + 2)*65 + px] = c.x;
        epi[(lane*4 + 3)*65 + px] = c.y;
    }
    __syncthreads();
    for (int i = t; i < 8192; i += 256) {
        const int o = i >> 6, px = i & 63;
        out[(((size_t)b*128 + o)*64 + y)*64 + px] = epi[o*65 + px] + __ldg(bdc + o);
    }
}

// ---------------- launch ----------------
extern "C" void kernel_launch(void* const* d_in, const int* in_sizes, int n_in,
                              void* d_out, int out_size)
{
    const float* x     = (const float*)d_in[0];
    const float* gam   = (const float*)d_in[1];
    const float* bet   = (const float*)d_in[2];
    const float* mea   = (const float*)d_in[3];
    const float* var   = (const float*)d_in[4];
    const float* woff  = (const float*)d_in[5];
    const float* boff  = (const float*)d_in[6];
    const float* wdc   = (const float*)d_in[7];
    const float* bdc   = (const float*)d_in[8];
    float* out = (float*)d_out;

    static bool attr_done = false;
    if (!attr_done) {
        cudaFuncSetAttribute(k_off,    cudaFuncAttributeMaxDynamicSharedMemorySize, 64*132*4 + 6912*4);
        cudaFuncSetAttribute(k_deform, cudaFuncAttributeMaxDynamicSharedMemorySize, (8192+16384+1152)*4);
        attr_done = true;
    }

    k_prep<<<(9*128*32 + 255)/256, 256>>>(woff, wdc);
    k_bnrelu<<<dim3(8,64), 256>>>(x, gam, bet, mea, var);
    k_off<<<dim3(8,64), 256, 64*132*4 + 6912*4>>>(boff);
    k_deform<<<dim3(8,64), 256, (8192+16384+1152)*4>>>(bdc, out);
}

// round 9
// speedup vs baseline: 1.5741x; 1.5741x over previous
#include <cuda_runtime.h>
#include <cuda_bf16.h>
#include <cstdint>

typedef unsigned long long ull;

#define EPSV 1e-5f

// ---------------- device scratch (no allocations allowed) ----------------
__device__ float  g_h[8*64*64*128];        // BN-ReLU output NHWC [b][y][x][c]
__device__ float  g_off[8*64*64*18];       // offsets [b][y][x][18]
__device__ float2 g_woff2[9*64*18];        // w_off repack [tap][c2][oc]
__device__ float  g_wtf[9*16384];          // w_dconv per-tap [k][o*128+c], tf32-rounded

// ---------------- f32x2 helpers (k_off) ----------------
__device__ __forceinline__ ull f32x2_add(ull a, ull b){
    ull r; asm("add.rn.f32x2 %0, %1, %2;" : "=l"(r) : "l"(a), "l"(b)); return r;
}
__device__ __forceinline__ void f32x2_fma(ull &d, ull a, ull b){
    asm("fma.rn.f32x2 %0, %1, %2, %0;" : "+l"(d) : "l"(a), "l"(b));
}
__device__ __forceinline__ float2 f32x2_unpack(ull v){
    float2 f; asm("mov.b64 {%0, %1}, %2;" : "=f"(f.x), "=f"(f.y) : "l"(v)); return f;
}
__device__ __forceinline__ void lds_2u64(ull &a, ull &b, uint32_t addr){
    asm volatile("ld.shared.v2.b64 {%0, %1}, [%2];" : "=l"(a), "=l"(b) : "r"(addr));
}

// ---------------- tf32 helpers (baseline PTX, no sm_103a features) ----------------
__device__ __forceinline__ float cvt_tf32(float x){
    uint32_t r; asm("cvt.rna.tf32.f32 %0, %1;" : "=r"(r) : "f"(x));
    return __uint_as_float(r);
}
__device__ __forceinline__ void mma_tf32(float& c0, float& c1, float& c2, float& c3,
                                         uint32_t a0, uint32_t a1, uint32_t a2, uint32_t a3,
                                         uint32_t b0, uint32_t b1){
    asm volatile("mma.sync.aligned.m16n8k8.row.col.f32.tf32.tf32.f32 "
        "{%0,%1,%2,%3}, {%4,%5,%6,%7}, {%8,%9}, {%0,%1,%2,%3};"
        : "+f"(c0), "+f"(c1), "+f"(c2), "+f"(c3)
        : "r"(a0), "r"(a1), "r"(a2), "r"(a3), "r"(b0), "r"(b1));
}

// ---------------- kernel 0: weight repack ----------------
__global__ void k_prep(const float* __restrict__ woff, const float* __restrict__ wdc)
{
    int i = blockIdx.x*256 + threadIdx.x;
    if (i < 9*64*18) {
        int tap = i / 1152;
        int r   = i - tap*1152;
        int c2  = r / 18, oc = r - c2*18;
        g_woff2[i] = make_float2(woff[(oc*128 + 2*c2    )*9 + tap],
                                 woff[(oc*128 + 2*c2 + 1)*9 + tap]);
    }
    if (i < 9*128*128) {
        int k = i / 16384;
        int r = i - k*16384;        // r = o*128 + c
        g_wtf[k*16384 + r] = cvt_tf32(wdc[(size_t)r*9 + k]);
    }
}

// ---------------- kernel 1: BN + ReLU, NCHW -> NHWC ----------------
__global__ __launch_bounds__(256) void k_bnrelu(const float* __restrict__ x,
    const float* __restrict__ gam, const float* __restrict__ bet,
    const float* __restrict__ mea, const float* __restrict__ var)
{
    __shared__ float s[128*65];
    const int t = threadIdx.x;
    const int b = blockIdx.x, y = blockIdx.y;
    #pragma unroll
    for (int i0 = 0; i0 < 8192; i0 += 256) {
        int i = i0 + t;
        int c = i >> 6, xx = i & 63;
        float val = x[(((size_t)b*128 + c)*64 + y)*64 + xx];
        float inv = __ldg(gam + c) * rsqrtf(__ldg(var + c) + EPSV);
        s[c*65 + xx] = fmaxf((val - __ldg(mea + c)) * inv + __ldg(bet + c), 0.f);
    }
    __syncthreads();
    float* hrow = g_h + ((size_t)b*64 + y)*64*128;
    #pragma unroll
    for (int i0 = 0; i0 < 8192; i0 += 256) {
        int i = i0 + t;
        int xx = i >> 7, c = i & 127;
        hrow[xx*128 + c] = s[c*65 + xx];
    }
}

// ---------------- kernel 2: offset conv (18 out channels) ----------------
__global__ __launch_bounds__(256, 2) void k_off(const float* __restrict__ boff)
{
    extern __shared__ float sm2[];
    float* vrow = sm2;            // 64*132 floats
    float* wk   = sm2 + 64*132;   // 3*64*18 float2
    const int t = threadIdx.x;
    const int b = blockIdx.x, y = blockIdx.y;
    const int px = t >> 2, sl = t & 3;
    const uint32_t vrb = (uint32_t)__cvta_generic_to_shared(vrow);
    const uint32_t wkb = (uint32_t)__cvta_generic_to_shared(wk);

    ull acc[18];
    #pragma unroll
    for (int o = 0; o < 18; ++o) acc[o] = 0ull;

    for (int ky = 0; ky < 3; ++ky) {
        __syncthreads();
        const int yy = y + ky - 1;
        if ((unsigned)yy < 64u) {
            const float* src = g_h + ((size_t)b*64 + yy)*64*128;
            for (int i = t; i < 8192; i += 256) vrow[(i>>7)*132 + (i&127)] = src[i];
        } else {
            for (int i = t; i < 8192; i += 256) vrow[(i>>7)*132 + (i&127)] = 0.f;
        }
        {
            float4* dst = (float4*)wk;
            const float4* s = (const float4*)(g_woff2 + ky*3*64*18);
            for (int i = t; i < 1728; i += 256) dst[i] = s[i];
        }
        __syncthreads();
        #pragma unroll
        for (int kx = 0; kx < 3; ++kx) {
            const int xx = px + kx - 1;
            const bool valid = (unsigned)xx < 64u;
            const uint32_t vba = vrb + (uint32_t)xx*528u;
            #pragma unroll
            for (int c2p = 0; c2p < 16; ++c2p) {
                const int c2 = c2p*4 + sl;
                ull v = 0ull;
                if (valid)
                    asm volatile("ld.shared.b64 %0, [%1];" : "=l"(v) : "r"(vba + (uint32_t)c2*8u));
                const uint32_t wa = wkb + (uint32_t)((kx*64 + c2)*144);
                #pragma unroll
                for (int oq = 0; oq < 9; ++oq) {
                    ull wA, wB;
                    lds_2u64(wA, wB, wa + (uint32_t)oq*16u);
                    f32x2_fma(acc[2*oq  ], v, wA);
                    f32x2_fma(acc[2*oq+1], v, wB);
                }
            }
        }
    }
    #pragma unroll
    for (int o = 0; o < 18; ++o) {
        ull v = acc[o];
        v = f32x2_add(v, __shfl_xor_sync(0xFFFFFFFFu, v, 1));
        v = f32x2_add(v, __shfl_xor_sync(0xFFFFFFFFu, v, 2));
        acc[o] = v;
    }
    if (sl == 0) {
        float* orow = g_off + (((size_t)b*64 + y)*64 + px)*18;
        #pragma unroll
        for (int o = 0; o < 18; ++o) {
            float2 f = f32x2_unpack(acc[o]);
            orow[o] = f.x + f.y + __ldg(boff + o);
        }
    }
}

// ---------------- kernel 3: deformable conv via mma.sync tf32 ----------------
// grid (8, 32): one (batch, row-pair) per CTA. M=128 px, N=128 o, K=9*128.
// 512 thr = 16 warps, warp tile 32px x 32o (2 m-tiles x 4 n-tiles of m16n8k8).
// smem: A [px][c] stride 132 (67584B) | W [o][c] stride 132 (67584B) | offs (9216B)
#define SMA_BYTES 67584
#define SM3_TOTAL (67584*2 + 9216)

__global__ __launch_bounds__(512, 1) void k_deform_mma(const float* __restrict__ bdc,
                                                       float* __restrict__ out)
{
    extern __shared__ float smem[];
    float* As   = smem;                  // 128*132
    float* Ws   = smem + 16896;          // 128*132
    float* offs = smem + 33792;          // 2304
    const int t = threadIdx.x, warp = t >> 5, lane = t & 31;
    const int r = lane >> 2, tig = lane & 3;
    const int b = blockIdx.x, y0 = blockIdx.y * 2;
    const int mbase = (warp & 3) * 32;
    const int nbase = (warp >> 2) * 32;

    {
        const float* orow = g_off + ((size_t)b*64 + y0)*64*18;
        for (int i = t; i < 2304; i += 512) offs[i] = orow[i];
    }

    float acc[2][4][4];
    #pragma unroll
    for (int mt = 0; mt < 2; ++mt)
        #pragma unroll
        for (int nt = 0; nt < 4; ++nt)
            #pragma unroll
            for (int q = 0; q < 4; ++q) acc[mt][nt][q] = 0.f;

    const float* hb = g_h + (size_t)b*4096*128 + lane*4;

    for (int k = 0; k < 9; ++k) {
        __syncthreads();   // all warps done reading prev tap's tiles (covers offs on k==0)
        // stage W_k: [o][c] stride 132, coalesced
        {
            const float4* src = (const float4*)(g_wtf + k*16384);
            for (int i4 = t; i4 < 4096; i4 += 512) {
                int o = i4 >> 5, c = (i4 & 31) * 4;
                *(float4*)(Ws + o*132 + c) = src[i4];
            }
        }
        // gather bilinear samples -> A tile. warp handles px = pp*16 + warp.
        const int ky = k/3 - 1, kx = k - (k/3)*3 - 1;
        #pragma unroll
        for (int pp = 0; pp < 8; ++pp) {
            const int px = pp*16 + warp;
            const int row = y0 + (px >> 6), xx = px & 63;
            const float dy = offs[px*18 + 2*k];
            const float dx = offs[px*18 + 2*k + 1];
            const float py  = (float)(row + ky) + dy;
            const float pxf = (float)(xx  + kx) + dx;
            const float fy = floorf(py), fx = floorf(pxf);
            const int yi = (int)fy, xi = (int)fx;
            const float wy = py - fy, wx = pxf - fx;
            const float w00 = (1.f-wy)*(1.f-wx), w01 = (1.f-wy)*wx;
            const float w10 = wy*(1.f-wx),       w11 = wy*wx;
            float4 rv = make_float4(0.f,0.f,0.f,0.f);
            if ((unsigned)yi < 64u) {
                const float* rp = hb + (size_t)yi*8192;
                if ((unsigned)xi     < 64u) { float4 c = *(const float4*)(rp + xi*128);
                    rv.x += w00*c.x; rv.y += w00*c.y; rv.z += w00*c.z; rv.w += w00*c.w; }
                if ((unsigned)(xi+1) < 64u) { float4 c = *(const float4*)(rp + (xi+1)*128);
                    rv.x += w01*c.x; rv.y += w01*c.y; rv.z += w01*c.z; rv.w += w01*c.w; }
            }
            if ((unsigned)(yi+1) < 64u) {
                const float* rp = hb + (size_t)(yi+1)*8192;
                if ((unsigned)xi     < 64u) { float4 c = *(const float4*)(rp + xi*128);
                    rv.x += w10*c.x; rv.y += w10*c.y; rv.z += w10*c.z; rv.w += w10*c.w; }
                if ((unsigned)(xi+1) < 64u) { float4 c = *(const float4*)(rp + (xi+1)*128);
                    rv.x += w11*c.x; rv.y += w11*c.y; rv.z += w11*c.z; rv.w += w11*c.w; }
            }
            rv.x = cvt_tf32(rv.x); rv.y = cvt_tf32(rv.y);
            rv.z = cvt_tf32(rv.z); rv.w = cvt_tf32(rv.w);
            *(float4*)(As + px*132 + lane*4) = rv;
        }
        __syncthreads();
        // warp GEMM: 16 k-steps, 2 m-tiles x 4 n-tiles
        #pragma unroll 4
        for (int s = 0; s < 16; ++s) {
            uint32_t a[2][4];
            #pragma unroll
            for (int mt = 0; mt < 2; ++mt) {
                const float* ap = As + (mbase + mt*16 + r)*132 + s*8 + tig;
                a[mt][0] = __float_as_uint(ap[0]);
                a[mt][1] = __float_as_uint(ap[8*132]);
                a[mt][2] = __float_as_uint(ap[4]);
                a[mt][3] = __float_as_uint(ap[8*132 + 4]);
            }
            uint32_t bb[4][2];
            #pragma unroll
            for (int nt = 0; nt < 4; ++nt) {
                const float* bp = Ws + (nbase + nt*8 + r)*132 + s*8 + tig;
                bb[nt][0] = __float_as_uint(bp[0]);
                bb[nt][1] = __float_as_uint(bp[4]);
            }
            #pragma unroll
            for (int mt = 0; mt < 2; ++mt)
                #pragma unroll
                for (int nt = 0; nt < 4; ++nt)
                    mma_tf32(acc[mt][nt][0], acc[mt][nt][1], acc[mt][nt][2], acc[mt][nt][3],
                             a[mt][0], a[mt][1], a[mt][2], a[mt][3], bb[nt][0], bb[nt][1]);
        }
    }
    __syncthreads();
    // epilogue: acc -> smem [o][px] (reuse A region) -> coalesced NCHW stores
    float* epi = As;
    #pragma unroll
    for (int mt = 0; mt < 2; ++mt)
        #pragma unroll
        for (int nt = 0; nt < 4; ++nt) {
            const int col0 = nbase + nt*8 + 2*tig;
            const int px0  = mbase + mt*16 + r;
            epi[ col0   *132 + px0    ] = acc[mt][nt][0];
            epi[(col0+1)*132 + px0    ] = acc[mt][nt][1];
            epi[ col0   *132 + px0 + 8] = acc[mt][nt][2];
            epi[(col0+1)*132 + px0 + 8] = acc[mt][nt][3];
        }
    __syncthreads();
    for (int i = t; i < 16384; i += 512) {
        const int o = i >> 7, px = i & 127;
        const int row = y0 + (px >> 6), xx = px & 63;
        out[(((size_t)b*128 + o)*64 + row)*64 + xx] = epi[o*132 + px] + __ldg(bdc + o);
    }
}

// ---------------- launch ----------------
extern "C" void kernel_launch(void* const* d_in, const int* in_sizes, int n_in,
                              void* d_out, int out_size)
{
    const float* x     = (const float*)d_in[0];
    const float* gam   = (const float*)d_in[1];
    const float* bet   = (const float*)d_in[2];
    const float* mea   = (const float*)d_in[3];
    const float* var   = (const float*)d_in[4];
    const float* woff  = (const float*)d_in[5];
    const float* boff  = (const float*)d_in[6];
    const float* wdc   = (const float*)d_in[7];
    const float* bdc   = (const float*)d_in[8];
    float* out = (float*)d_out;

    cudaFuncSetAttribute(k_off,        cudaFuncAttributeMaxDynamicSharedMemorySize, 64*132*4 + 6912*4);
    cudaFuncSetAttribute(k_deform_mma, cudaFuncAttributeMaxDynamicSharedMemorySize, SM3_TOTAL);

    k_prep<<<(9*128*128 + 255)/256, 256>>>(woff, wdc);
    k_bnrelu<<<dim3(8,64), 256>>>(x, gam, bet, mea, var);
    k_off<<<dim3(8,64), 256, 64*132*4 + 6912*4>>>(boff);
    k_deform_mma<<<dim3(8,32), 512, SM3_TOTAL>>>(bdc, out);
}

// round 12
// speedup vs baseline: 2.1555x; 1.3694x over previous
#include <cuda_runtime.h>
#include <cuda_bf16.h>
#include <cstdint>

typedef unsigned long long ull;

#define EPSV 1e-5f

// ---------------- device scratch (no allocations allowed) ----------------
__device__ float g_h[8*64*64*128];      // BN-ReLU output NHWC [b][y][x][c]
__device__ float g_off[8*64*64*18];     // offsets [b][y][x][18]
__device__ float g_woffB[3*32*384];     // w_off repack [ky][oc(pad32)][kx*128+c], tf32
__device__ float g_wtf[9*16384];        // w_dconv per-tap [k][o*128+c], tf32

// ---------------- tf32 helpers (baseline PTX, no sm_103a features) ----------------
__device__ __forceinline__ float cvt_tf32(float x){
    uint32_t r; asm("cvt.rna.tf32.f32 %0, %1;" : "=r"(r) : "f"(x));
    return __uint_as_float(r);
}
__device__ __forceinline__ void mma_tf32(float& c0, float& c1, float& c2, float& c3,
                                         uint32_t a0, uint32_t a1, uint32_t a2, uint32_t a3,
                                         uint32_t b0, uint32_t b1){
    asm volatile("mma.sync.aligned.m16n8k8.row.col.f32.tf32.tf32.f32 "
        "{%0,%1,%2,%3}, {%4,%5,%6,%7}, {%8,%9}, {%0,%1,%2,%3};"
        : "+f"(c0), "+f"(c1), "+f"(c2), "+f"(c3)
        : "r"(a0), "r"(a1), "r"(a2), "r"(a3), "r"(b0), "r"(b1));
}

// ---------------- kernel 0: weight repack (tf32) ----------------
__global__ void k_prep(const float* __restrict__ woff, const float* __restrict__ wdc)
{
    int i = blockIdx.x*256 + threadIdx.x;
    if (i < 3*32*384) {
        int ky = i / 12288;
        int r  = i - ky*12288;
        int oc = r / 384;
        int kc = r - oc*384;
        int kx = kc >> 7, c = kc & 127;
        g_woffB[i] = (oc < 18) ? cvt_tf32(woff[(oc*128 + c)*9 + ky*3 + kx]) : 0.f;
    }
    if (i < 9*128*128) {
        int k = i / 16384;
        int r = i - k*16384;        // r = o*128 + c
        g_wtf[k*16384 + r] = cvt_tf32(wdc[(size_t)r*9 + k]);
    }
}

// ---------------- kernel 1: BN + ReLU, NCHW -> NHWC ----------------
__global__ __launch_bounds__(256) void k_bnrelu(const float* __restrict__ x,
    const float* __restrict__ gam, const float* __restrict__ bet,
    const float* __restrict__ mea, const float* __restrict__ var)
{
    __shared__ float s[128*65];
    const int t = threadIdx.x;
    const int b = blockIdx.x, y = blockIdx.y;
    #pragma unroll
    for (int i0 = 0; i0 < 8192; i0 += 256) {
        int i = i0 + t;
        int c = i >> 6, xx = i & 63;
        float val = x[(((size_t)b*128 + c)*64 + y)*64 + xx];
        float inv = __ldg(gam + c) * rsqrtf(__ldg(var + c) + EPSV);
        s[c*65 + xx] = fmaxf((val - __ldg(mea + c)) * inv + __ldg(bet + c), 0.f);
    }
    __syncthreads();
    float* hrow = g_h + ((size_t)b*64 + y)*64*128;
    #pragma unroll
    for (int i0 = 0; i0 < 8192; i0 += 256) {
        int i = i0 + t;
        int xx = i >> 7, c = i & 127;
        hrow[xx*128 + c] = s[c*65 + xx];
    }
}

// ---------------- kernel 2: offset conv via mma.sync tf32 ----------------
// grid (8,64): one (b,row) per CTA, 256 thr = 8 warps, 2 CTAs/SM.
// M=64 px, N=32 (18 used), K=3ky*3kx*128c. A = shifted row window vrow[66][132]
// (kx via slot offset), B = per-ky weights [32][388].
#define SMO_TOTAL ((66*132 + 32*388)*4)
__global__ __launch_bounds__(256, 2) void k_off_mma(const float* __restrict__ boff)
{
    extern __shared__ float smo[];
    float* vrow = smo;          // 66*132
    float* Bs   = smo + 8712;   // 32*388
    const int t = threadIdx.x, warp = t >> 5, lane = t & 31;
    const int r = lane >> 2, tig = lane & 3;
    const int b = blockIdx.x, y = blockIdx.y;
    const int mbase = (warp & 3) * 16;
    const int nbase = (warp >> 2) * 16;

    float acc[2][4];
    #pragma unroll
    for (int nt = 0; nt < 2; ++nt)
        #pragma unroll
        for (int q = 0; q < 4; ++q) acc[nt][q] = 0.f;

    for (int ky = 0; ky < 3; ++ky) {
        __syncthreads();
        const int yy = y + ky - 1;
        const bool rowok = (unsigned)yy < 64u;
        const float* srcrow = g_h + ((size_t)b*64 + yy)*64*128;
        // stage vrow slots 0..65 (slot = x+1), tf32-rounded
        for (int i4 = t; i4 < 2112; i4 += 256) {
            int slot = i4 >> 5, c = (i4 & 31) * 4;
            int xx = slot - 1;
            float4 v = make_float4(0.f,0.f,0.f,0.f);
            if (rowok && (unsigned)xx < 64u) {
                v = *(const float4*)(srcrow + xx*128 + c);
                v.x = cvt_tf32(v.x); v.y = cvt_tf32(v.y);
                v.z = cvt_tf32(v.z); v.w = cvt_tf32(v.w);
            }
            *(float4*)(vrow + slot*132 + c) = v;
        }
        // stage B_ky [oc][kx*128+c], stride 388 (conflict-free frag loads)
        for (int i4 = t; i4 < 3072; i4 += 256) {
            int oc = i4 / 96, rem = i4 - oc*96;
            *(float4*)(Bs + oc*388 + rem*4) =
                ((const float4*)(g_woffB + ky*12288 + oc*384))[rem];
        }
        __syncthreads();
        #pragma unroll
        for (int kx = 0; kx < 3; ++kx) {
            #pragma unroll 4
            for (int s = 0; s < 16; ++s) {
                const float* ap = vrow + (mbase + r + kx)*132 + s*8 + tig;
                uint32_t a0 = __float_as_uint(ap[0]);
                uint32_t a1 = __float_as_uint(ap[8*132]);
                uint32_t a2 = __float_as_uint(ap[4]);
                uint32_t a3 = __float_as_uint(ap[8*132 + 4]);
                #pragma unroll
                for (int nt = 0; nt < 2; ++nt) {
                    const float* bp = Bs + (nbase + nt*8 + r)*388 + kx*128 + s*8 + tig;
                    mma_tf32(acc[nt][0], acc[nt][1], acc[nt][2], acc[nt][3],
                             a0, a1, a2, a3,
                             __float_as_uint(bp[0]), __float_as_uint(bp[4]));
                }
            }
        }
    }
    // epilogue: direct scattered stores (tiny: 1152 floats per CTA)
    float* orow = g_off + ((size_t)b*64 + y)*64*18;
    const int px0 = mbase + r;
    #pragma unroll
    for (int nt = 0; nt < 2; ++nt) {
        const int oc0 = nbase + nt*8 + 2*tig;
        if (oc0 < 18) {
            float bias = __ldg(boff + oc0);
            orow[ px0     *18 + oc0] = acc[nt][0] + bias;
            orow[(px0 + 8)*18 + oc0] = acc[nt][2] + bias;
        }
        if (oc0 + 1 < 18) {
            float bias = __ldg(boff + oc0 + 1);
            orow[ px0     *18 + oc0 + 1] = acc[nt][1] + bias;
            orow[(px0 + 8)*18 + oc0 + 1] = acc[nt][3] + bias;
        }
    }
}

// ---------------- kernel 3: deformable conv via mma.sync tf32 ----------------
// grid (8,64): one (b,row) per CTA. M=64 px, N=128 o, K=9*128. 256 thr = 8 warps,
// warp tile 32px x 32o, 2 CTAs/SM for cross-CTA gather/GEMM overlap.
#define SMD_TOTAL ((64*132 + 128*132 + 64*18)*4)
__global__ __launch_bounds__(256, 2) void k_deform_mma(const float* __restrict__ bdc,
                                                       float* __restrict__ out)
{
    extern __shared__ float smd[];
    float* As   = smd;                      // 64*132
    float* Ws   = smd + 64*132;             // 128*132
    float* offs = smd + 64*132 + 128*132;   // 64*18
    const int t = threadIdx.x, warp = t >> 5, lane = t & 31;
    const int r = lane >> 2, tig = lane & 3;
    const int b = blockIdx.x, y = blockIdx.y;
    const int mbase = (warp & 1) * 32;
    const int nbase = (warp >> 1) * 32;

    {
        const float* orow = g_off + ((size_t)b*64 + y)*64*18;
        for (int i = t; i < 1152; i += 256) offs[i] = orow[i];
    }

    float acc[2][4][4];
    #pragma unroll
    for (int mt = 0; mt < 2; ++mt)
        #pragma unroll
        for (int nt = 0; nt < 4; ++nt)
            #pragma unroll
            for (int q = 0; q < 4; ++q) acc[mt][nt][q] = 0.f;

    const float* hb = g_h + (size_t)b*4096*128 + lane*4;

    for (int k = 0; k < 9; ++k) {
        __syncthreads();   // prev tap fully consumed (covers offs staging on k==0)
        // stage W_k [o][c] stride 132
        {
            const float4* src = (const float4*)(g_wtf + k*16384);
            for (int i4 = t; i4 < 4096; i4 += 256) {
                int o = i4 >> 5, c = (i4 & 31) * 4;
                *(float4*)(Ws + o*132 + c) = src[i4];
            }
        }
        // gather bilinear samples -> A tile; warp owns px = pp*8 + warp
        const int ky = k/3 - 1, kx = k - (k/3)*3 - 1;
        #pragma unroll
        for (int pp = 0; pp < 8; ++pp) {
            const int px = pp*8 + warp;
            const float dy = offs[px*18 + 2*k];
            const float dx = offs[px*18 + 2*k + 1];
            const float py  = (float)(y  + ky) + dy;
            const float pxf = (float)(px + kx) + dx;
            const float fy = floorf(py), fx = floorf(pxf);
            const int yi = (int)fy, xi = (int)fx;
            const float wy = py - fy, wx = pxf - fx;
            const float w00 = (1.f-wy)*(1.f-wx), w01 = (1.f-wy)*wx;
            const float w10 = wy*(1.f-wx),       w11 = wy*wx;
            float4 rv = make_float4(0.f,0.f,0.f,0.f);
            if ((unsigned)yi < 64u) {
                const float* rp = hb + (size_t)yi*8192;
                if ((unsigned)xi     < 64u) { float4 c = *(const float4*)(rp + xi*128);
                    rv.x += w00*c.x; rv.y += w00*c.y; rv.z += w00*c.z; rv.w += w00*c.w; }
                if ((unsigned)(xi+1) < 64u) { float4 c = *(const float4*)(rp + (xi+1)*128);
                    rv.x += w01*c.x; rv.y += w01*c.y; rv.z += w01*c.z; rv.w += w01*c.w; }
            }
            if ((unsigned)(yi+1) < 64u) {
                const float* rp = hb + (size_t)(yi+1)*8192;
                if ((unsigned)xi     < 64u) { float4 c = *(const float4*)(rp + xi*128);
                    rv.x += w10*c.x; rv.y += w10*c.y; rv.z += w10*c.z; rv.w += w10*c.w; }
                if ((unsigned)(xi+1) < 64u) { float4 c = *(const float4*)(rp + (xi+1)*128);
                    rv.x += w11*c.x; rv.y += w11*c.y; rv.z += w11*c.z; rv.w += w11*c.w; }
            }
            rv.x = cvt_tf32(rv.x); rv.y = cvt_tf32(rv.y);
            rv.z = cvt_tf32(rv.z); rv.w = cvt_tf32(rv.w);
            *(float4*)(As + px*132 + lane*4) = rv;
        }
        __syncthreads();
        // warp GEMM: 16 k-steps, 2 m-tiles x 4 n-tiles
        #pragma unroll 4
        for (int s = 0; s < 16; ++s) {
            uint32_t a[2][4];
            #pragma unroll
            for (int mt = 0; mt < 2; ++mt) {
                const float* ap = As + (mbase + mt*16 + r)*132 + s*8 + tig;
                a[mt][0] = __float_as_uint(ap[0]);
                a[mt][1] = __float_as_uint(ap[8*132]);
                a[mt][2] = __float_as_uint(ap[4]);
                a[mt][3] = __float_as_uint(ap[8*132 + 4]);
            }
            uint32_t bb[4][2];
            #pragma unroll
            for (int nt = 0; nt < 4; ++nt) {
                const float* bp = Ws + (nbase + nt*8 + r)*132 + s*8 + tig;
                bb[nt][0] = __float_as_uint(bp[0]);
                bb[nt][1] = __float_as_uint(bp[4]);
            }
            #pragma unroll
            for (int mt = 0; mt < 2; ++mt)
                #pragma unroll
                for (int nt = 0; nt < 4; ++nt)
                    mma_tf32(acc[mt][nt][0], acc[mt][nt][1], acc[mt][nt][2], acc[mt][nt][3],
                             a[mt][0], a[mt][1], a[mt][2], a[mt][3], bb[nt][0], bb[nt][1]);
        }
    }
    __syncthreads();
    // epilogue: acc -> smem [o][px] stride 68 (conflict-free) -> coalesced NCHW
    float* epi = As;   // 128*68 floats = 34816B, fits in As+Ws region
    #pragma unroll
    for (int mt = 0; mt < 2; ++mt)
        #pragma unroll
        for (int nt = 0; nt < 4; ++nt) {
            const int col0 = nbase + nt*8 + 2*tig;
            const int px0  = mbase + mt*16 + r;
            epi[ col0   *68 + px0    ] = acc[mt][nt][0];
            epi[(col0+1)*68 + px0    ] = acc[mt][nt][1];
            epi[ col0   *68 + px0 + 8] = acc[mt][nt][2];
            epi[(col0+1)*68 + px0 + 8] = acc[mt][nt][3];
        }
    __syncthreads();
    for (int i = t; i < 8192; i += 256) {
        const int o = i >> 6, px = i & 63;
        out[(((size_t)b*128 + o)*64 + y)*64 + px] = epi[o*68 + px] + __ldg(bdc + o);
    }
}

// ---------------- launch ----------------
extern "C" void kernel_launch(void* const* d_in, const int* in_sizes, int n_in,
                              void* d_out, int out_size)
{
    const float* x     = (const float*)d_in[0];
    const float* gam   = (const float*)d_in[1];
    const float* bet   = (const float*)d_in[2];
    const float* mea   = (const float*)d_in[3];
    const float* var   = (const float*)d_in[4];
    const float* woff  = (const float*)d_in[5];
    const float* boff  = (const float*)d_in[6];
    const float* wdc   = (const float*)d_in[7];
    const float* bdc   = (const float*)d_in[8];
    float* out = (float*)d_out;

    cudaFuncSetAttribute(k_off_mma,    cudaFuncAttributeMaxDynamicSharedMemorySize, SMO_TOTAL);
    cudaFuncSetAttribute(k_deform_mma, cudaFuncAttributeMaxDynamicSharedMemorySize, SMD_TOTAL);

    k_prep<<<(9*128*128 + 255)/256, 256>>>(woff, wdc);
    k_bnrelu<<<dim3(8,64), 256>>>(x, gam, bet, mea, var);
    k_off_mma<<<dim3(8,64), 256, SMO_TOTAL>>>(boff);
    k_deform_mma<<<dim3(8,64), 256, SMD_TOTAL>>>(bdc, out);
}

// round 13
// speedup vs baseline: 2.2855x; 1.0603x over previous
#include <cuda_runtime.h>
#include <cuda_bf16.h>
#include <cstdint>

typedef unsigned long long ull;

#define EPSV 1e-5f

// ---------------- device scratch (no allocations allowed) ----------------
__device__ float g_h[8*64*64*128];      // BN-ReLU output NHWC [b][y][x][c]
__device__ float g_off[8*64*64*18];     // offsets [b][y][x][18]
__device__ float g_woffB[3*32*384];     // w_off repack [ky][oc(pad32)][kx*128+c], tf32
__device__ float g_wtf[9*16384];        // w_dconv per-tap [k][o*128+cperm], tf32, cols permuted [0,4,1,5,2,6,3,7]

// ---------------- tf32 helpers (baseline PTX, no sm_103a features) ----------------
__device__ __forceinline__ float cvt_tf32(float x){
    uint32_t r; asm("cvt.rna.tf32.f32 %0, %1;" : "=r"(r) : "f"(x));
    return __uint_as_float(r);
}
__device__ __forceinline__ void mma_tf32(float& c0, float& c1, float& c2, float& c3,
                                         uint32_t a0, uint32_t a1, uint32_t a2, uint32_t a3,
                                         uint32_t b0, uint32_t b1){
    asm volatile("mma.sync.aligned.m16n8k8.row.col.f32.tf32.tf32.f32 "
        "{%0,%1,%2,%3}, {%4,%5,%6,%7}, {%8,%9}, {%0,%1,%2,%3};"
        : "+f"(c0), "+f"(c1), "+f"(c2), "+f"(c3)
        : "r"(a0), "r"(a1), "r"(a2), "r"(a3), "r"(b0), "r"(b1));
}
__device__ __forceinline__ void cp_async16(uint32_t dst, const void* src){
    asm volatile("cp.async.cg.shared.global [%0], [%1], 16;" :: "r"(dst), "l"(src));
}
#define CP_ASYNC_COMMIT() asm volatile("cp.async.commit_group;" ::: "memory")
#define CP_ASYNC_WAIT0()  asm volatile("cp.async.wait_group 0;" ::: "memory")

// ---------------- kernel 0: weight repack (tf32) ----------------
__global__ void k_prep(const float* __restrict__ woff, const float* __restrict__ wdc)
{
    int i = blockIdx.x*256 + threadIdx.x;
    if (i < 3*32*384) {
        int ky = i / 12288;
        int r  = i - ky*12288;
        int oc = r / 384;
        int kc = r - oc*384;
        int kx = kc >> 7, c = kc & 127;
        g_woffB[i] = (oc < 18) ? cvt_tf32(woff[(oc*128 + c)*9 + ky*3 + kx]) : 0.f;
    }
    if (i < 9*128*128) {
        int k = i / 16384;
        int r = i - k*16384;        // r = o*128 + cpos
        int o = r >> 7, cpos = r & 127;
        int g = cpos >> 3, p = cpos & 7;
        int w = (p >> 1) + (p & 1)*4;   // inverse of perm [0,4,1,5,2,6,3,7]
        g_wtf[i] = cvt_tf32(wdc[(size_t)(o*128 + g*8 + w)*9 + k]);
    }
}

// ---------------- kernel 1: BN + ReLU, NCHW -> NHWC ----------------
__global__ __launch_bounds__(256) void k_bnrelu(const float* __restrict__ x,
    const float* __restrict__ gam, const float* __restrict__ bet,
    const float* __restrict__ mea, const float* __restrict__ var)
{
    __shared__ float s[128*65];
    const int t = threadIdx.x;
    const int b = blockIdx.x, y = blockIdx.y;
    #pragma unroll
    for (int i0 = 0; i0 < 8192; i0 += 256) {
        int i = i0 + t;
        int c = i >> 6, xx = i & 63;
        float val = x[(((size_t)b*128 + c)*64 + y)*64 + xx];
        float inv = __ldg(gam + c) * rsqrtf(__ldg(var + c) + EPSV);
        s[c*65 + xx] = fmaxf((val - __ldg(mea + c)) * inv + __ldg(bet + c), 0.f);
    }
    __syncthreads();
    float* hrow = g_h + ((size_t)b*64 + y)*64*128;
    #pragma unroll
    for (int i0 = 0; i0 < 8192; i0 += 256) {
        int i = i0 + t;
        int xx = i >> 7, c = i & 127;
        hrow[xx*128 + c] = s[c*65 + xx];
    }
}

// ---------------- kernel 2: offset conv via mma.sync tf32 ----------------
// grid (8,64): one (b,row) per CTA, 256 thr = 8 warps, 2 CTAs/SM.
#define SMO_TOTAL ((66*132 + 32*388)*4)
__global__ __launch_bounds__(256, 2) void k_off_mma(const float* __restrict__ boff)
{
    extern __shared__ float smo[];
    float* vrow = smo;          // 66*132
    float* Bs   = smo + 8712;   // 32*388
    const int t = threadIdx.x, warp = t >> 5, lane = t & 31;
    const int r = lane >> 2, tig = lane & 3;
    const int b = blockIdx.x, y = blockIdx.y;
    const int mbase = (warp & 3) * 16;
    const int nbase = (warp >> 2) * 16;

    float acc[2][4];
    #pragma unroll
    for (int nt = 0; nt < 2; ++nt)
        #pragma unroll
        for (int q = 0; q < 4; ++q) acc[nt][q] = 0.f;

    for (int ky = 0; ky < 3; ++ky) {
        __syncthreads();
        const int yy = y + ky - 1;
        const bool rowok = (unsigned)yy < 64u;
        const float* srcrow = g_h + ((size_t)b*64 + yy)*64*128;
        for (int i4 = t; i4 < 2112; i4 += 256) {
            int slot = i4 >> 5, c = (i4 & 31) * 4;
            int xx = slot - 1;
            float4 v = make_float4(0.f,0.f,0.f,0.f);
            if (rowok && (unsigned)xx < 64u) {
                v = *(const float4*)(srcrow + xx*128 + c);
                v.x = cvt_tf32(v.x); v.y = cvt_tf32(v.y);
                v.z = cvt_tf32(v.z); v.w = cvt_tf32(v.w);
            }
            *(float4*)(vrow + slot*132 + c) = v;
        }
        for (int i4 = t; i4 < 3072; i4 += 256) {
            int oc = i4 / 96, rem = i4 - oc*96;
            *(float4*)(Bs + oc*388 + rem*4) =
                ((const float4*)(g_woffB + ky*12288 + oc*384))[rem];
        }
        __syncthreads();
        #pragma unroll
        for (int kx = 0; kx < 3; ++kx) {
            #pragma unroll 4
            for (int s = 0; s < 16; ++s) {
                const float* ap = vrow + (mbase + r + kx)*132 + s*8 + tig;
                uint32_t a0 = __float_as_uint(ap[0]);
                uint32_t a1 = __float_as_uint(ap[8*132]);
                uint32_t a2 = __float_as_uint(ap[4]);
                uint32_t a3 = __float_as_uint(ap[8*132 + 4]);
                #pragma unroll
                for (int nt = 0; nt < 2; ++nt) {
                    const float* bp = Bs + (nbase + nt*8 + r)*388 + kx*128 + s*8 + tig;
                    mma_tf32(acc[nt][0], acc[nt][1], acc[nt][2], acc[nt][3],
                             a0, a1, a2, a3,
                             __float_as_uint(bp[0]), __float_as_uint(bp[4]));
                }
            }
        }
    }
    float* orow = g_off + ((size_t)b*64 + y)*64*18;
    const int px0 = mbase + r;
    #pragma unroll
    for (int nt = 0; nt < 2; ++nt) {
        const int oc0 = nbase + nt*8 + 2*tig;
        if (oc0 < 18) {
            float bias = __ldg(boff + oc0);
            orow[ px0     *18 + oc0] = acc[nt][0] + bias;
            orow[(px0 + 8)*18 + oc0] = acc[nt][2] + bias;
        }
        if (oc0 + 1 < 18) {
            float bias = __ldg(boff + oc0 + 1);
            orow[ px0     *18 + oc0 + 1] = acc[nt][1] + bias;
            orow[(px0 + 8)*18 + oc0 + 1] = acc[nt][3] + bias;
        }
    }
}

// ---------------- kernel 3: deformable conv via mma.sync tf32 + cp.async ----------------
// grid (8,64): one (b,row) per CTA. M=64 px, N=128 o, K=9*128. 256 thr = 8 warps,
// warp tile 32x32, 2 CTAs/SM. W_k staged by cp.async overlapped with the gather.
// Ws stride 136 floats (544B = 8 banks mod 32 -> b64 frag loads split into two
// clean 128B phases). B cols pre-permuted in g_wtf for (tig,tig+4) adjacency.
#define SMD_TOTAL ((64*132 + 128*136 + 64*18)*4)
__global__ __launch_bounds__(256, 2) void k_deform_mma(const float* __restrict__ bdc,
                                                       float* __restrict__ out)
{
    extern __shared__ float smd[];
    float* As   = smd;                      // 64*132
    float* Ws   = smd + 64*132;             // 128*136
    float* offs = smd + 64*132 + 128*136;   // 64*18
    const int t = threadIdx.x, warp = t >> 5, lane = t & 31;
    const int r = lane >> 2, tig = lane & 3;
    const int b = blockIdx.x, y = blockIdx.y;
    const int mbase = (warp & 1) * 32;
    const int nbase = (warp >> 1) * 32;
    const uint32_t ws_u32 = (uint32_t)__cvta_generic_to_shared(Ws);

    {
        const float* orow = g_off + ((size_t)b*64 + y)*64*18;
        for (int i = t; i < 1152; i += 256) offs[i] = orow[i];
    }

    float acc[2][4][4];
    #pragma unroll
    for (int mt = 0; mt < 2; ++mt)
        #pragma unroll
        for (int nt = 0; nt < 4; ++nt)
            #pragma unroll
            for (int q = 0; q < 4; ++q) acc[mt][nt][q] = 0.f;

    const float* hb = g_h + (size_t)b*4096*128 + lane*4;

    for (int k = 0; k < 9; ++k) {
        __syncthreads();   // prev tap fully consumed (covers offs staging on k==0)
        // launch async W_k staging (DMA overlaps the gather below)
        {
            const float* src = g_wtf + k*16384;
            #pragma unroll
            for (int j = 0; j < 16; ++j) {
                int i4 = j*256 + t;
                int o = i4 >> 5, c = (i4 & 31) * 4;
                cp_async16(ws_u32 + (uint32_t)(o*136 + c)*4u, src + i4*4);
            }
            CP_ASYNC_COMMIT();
        }
        // gather bilinear samples -> A tile; warp owns px = pp*8 + warp
        const int ky = k/3 - 1, kx = k - (k/3)*3 - 1;
        #pragma unroll
        for (int pp = 0; pp < 8; ++pp) {
            const int px = pp*8 + warp;
            const float dy = offs[px*18 + 2*k];
            const float dx = offs[px*18 + 2*k + 1];
            const float py  = (float)(y  + ky) + dy;
            const float pxf = (float)(px + kx) + dx;
            const float fy = floorf(py), fx = floorf(pxf);
            const int yi = (int)fy, xi = (int)fx;
            const float wy = py - fy, wx = pxf - fx;
            const float w00 = (1.f-wy)*(1.f-wx), w01 = (1.f-wy)*wx;
            const float w10 = wy*(1.f-wx),       w11 = wy*wx;
            float4 rv = make_float4(0.f,0.f,0.f,0.f);
            if ((unsigned)yi < 64u) {
                const float* rp = hb + (size_t)yi*8192;
                if ((unsigned)xi     < 64u) { float4 c = *(const float4*)(rp + xi*128);
                    rv.x += w00*c.x; rv.y += w00*c.y; rv.z += w00*c.z; rv.w += w00*c.w; }
                if ((unsigned)(xi+1) < 64u) { float4 c = *(const float4*)(rp + (xi+1)*128);
                    rv.x += w01*c.x; rv.y += w01*c.y; rv.z += w01*c.z; rv.w += w01*c.w; }
            }
            if ((unsigned)(yi+1) < 64u) {
                const float* rp = hb + (size_t)(yi+1)*8192;
                if ((unsigned)xi     < 64u) { float4 c = *(const float4*)(rp + xi*128);
                    rv.x += w10*c.x; rv.y += w10*c.y; rv.z += w10*c.z; rv.w += w10*c.w; }
                if ((unsigned)(xi+1) < 64u) { float4 c = *(const float4*)(rp + (xi+1)*128);
                    rv.x += w11*c.x; rv.y += w11*c.y; rv.z += w11*c.z; rv.w += w11*c.w; }
            }
            rv.x = cvt_tf32(rv.x); rv.y = cvt_tf32(rv.y);
            rv.z = cvt_tf32(rv.z); rv.w = cvt_tf32(rv.w);
            *(float4*)(As + px*132 + lane*4) = rv;
        }
        CP_ASYNC_WAIT0();
        __syncthreads();
        // warp GEMM: 16 k-steps, 2 m-tiles x 4 n-tiles; B frags as b64 pairs
        #pragma unroll 4
        for (int s = 0; s < 16; ++s) {
            uint32_t a[2][4];
            #pragma unroll
            for (int mt = 0; mt < 2; ++mt) {
                const float* ap = As + (mbase + mt*16 + r)*132 + s*8 + tig;
                a[mt][0] = __float_as_uint(ap[0]);
                a[mt][1] = __float_as_uint(ap[8*132]);
                a[mt][2] = __float_as_uint(ap[4]);
                a[mt][3] = __float_as_uint(ap[8*132 + 4]);
            }
            uint32_t bb[4][2];
            #pragma unroll
            for (int nt = 0; nt < 4; ++nt) {
                float2 bv = *(const float2*)(Ws + (nbase + nt*8 + r)*136 + s*8 + 2*tig);
                bb[nt][0] = __float_as_uint(bv.x);
                bb[nt][1] = __float_as_uint(bv.y);
            }
            #pragma unroll
            for (int mt = 0; mt < 2; ++mt)
                #pragma unroll
                for (int nt = 0; nt < 4; ++nt)
                    mma_tf32(acc[mt][nt][0], acc[mt][nt][1], acc[mt][nt][2], acc[mt][nt][3],
                             a[mt][0], a[mt][1], a[mt][2], a[mt][3], bb[nt][0], bb[nt][1]);
        }
    }
    __syncthreads();
    // epilogue: acc -> smem [o][px] stride 68 (conflict-free) -> coalesced NCHW
    float* epi = As;   // 128*68 floats, fits in As+Ws region
    #pragma unroll
    for (int mt = 0; mt < 2; ++mt)
        #pragma unroll
        for (int nt = 0; nt < 4; ++nt) {
            const int col0 = nbase + nt*8 + 2*tig;
            const int px0  = mbase + mt*16 + r;
            epi[ col0   *68 + px0    ] = acc[mt][nt][0];
            epi[(col0+1)*68 + px0    ] = acc[mt][nt][1];
            epi[ col0   *68 + px0 + 8] = acc[mt][nt][2];
            epi[(col0+1)*68 + px0 + 8] = acc[mt][nt][3];
        }
    __syncthreads();
    for (int i = t; i < 8192; i += 256) {
        const int o = i >> 6, px = i & 63;
        out[(((size_t)b*128 + o)*64 + y)*64 + px] = epi[o*68 + px] + __ldg(bdc + o);
    }
}

// ---------------- launch ----------------
extern "C" void kernel_launch(void* const* d_in, const int* in_sizes, int n_in,
                              void* d_out, int out_size)
{
    const float* x     = (const float*)d_in[0];
    const float* gam   = (const float*)d_in[1];
    const float* bet   = (const float*)d_in[2];
    const float* mea   = (const float*)d_in[3];
    const float* var   = (const float*)d_in[4];
    const float* woff  = (const float*)d_in[5];
    const float* boff  = (const float*)d_in[6];
    const float* wdc   = (const float*)d_in[7];
    const float* bdc   = (const float*)d_in[8];
    float* out = (float*)d_out;

    cudaFuncSetAttribute(k_off_mma,    cudaFuncAttributeMaxDynamicSharedMemorySize, SMO_TOTAL);
    cudaFuncSetAttribute(k_deform_mma, cudaFuncAttributeMaxDynamicSharedMemorySize, SMD_TOTAL);

    k_prep<<<(9*128*128 + 255)/256, 256>>>(woff, wdc);
    k_bnrelu<<<dim3(8,64), 256>>>(x, gam, bet, mea, var);
    k_off_mma<<<dim3(8,64), 256, SMO_TOTAL>>>(boff);
    k_deform_mma<<<dim3(8,64), 256, SMD_TOTAL>>>(bdc, out);
}